// round 16
// baseline (speedup 1.0000x reference)
#include <cuda_runtime.h>

// ---------------------------------------------------------------------------
// Fused spatio-temporal GCN, one 256-thread CTA per (b,t), 1 CTA/SM.
// cheb[0] = I shortcut (k=0 spatial GEMM replaced by acc := V0).
// Stage-3: 10 rows x 16 cols per thread (0.65 smem-lane-B/MAC, exact 170-row
// coverage), 2-way m-split assigned by WARP PARITY so all 4 SMSPs stay fed;
// cross-half reduce via smem. Stage-2: 6x8 tiles, c+=4 (proven R13 body).
// All operands smem-resident, cp.async prefetched, packed fma.rn.f32x2 math.
// ---------------------------------------------------------------------------

#define FINq 3
#define NV   170
#define CPAD 172          // cheb col pad (zeros at 170,171)
#define TMP  68           // Tm row pad (16B rows)
#define TTq  288
#define HH   64
#define OO   64
#define NT   256
#define S3R  10           // stage3 rows/thread (17 groups x 10 = 170 exact)
#define R2   6            // stage2 rows/thread (29 groups x 6 = 174)

typedef unsigned long long ull;

__device__ __forceinline__ ull f2fma(ull a, ull b, ull c) {
    ull d;
    asm("fma.rn.f32x2 %0, %1, %2, %3;" : "=l"(d) : "l"(a), "l"(b), "l"(c));
    return d;
}
__device__ __forceinline__ ull f2add(ull a, ull b) {
    ull d;
    asm("add.rn.f32x2 %0, %1, %2;" : "=l"(d) : "l"(a), "l"(b));
    return d;
}
__device__ __forceinline__ ull f2dup(float a) {
    ull d;
    asm("mov.b64 %0, {%1, %1};" : "=l"(d) : "f"(a));
    return d;
}
__device__ __forceinline__ float2 f2un(ull p) {
    float2 r;
    asm("mov.b64 {%0, %1}, %2;" : "=f"(r.x), "=f"(r.y) : "l"(p));
    return r;
}
__device__ __forceinline__ unsigned s2u(const void* p) {
    unsigned a;
    asm("{ .reg .u64 t; cvta.to.shared.u64 t, %1; cvt.u32.u64 %0, t; }"
        : "=r"(a) : "l"(p));
    return a;
}
#define CPA16(d, s) asm volatile("cp.async.cg.shared.global [%0], [%1], 16;" \
                                 :: "r"(d), "l"(s) : "memory")
#define CPCOMMIT()  asm volatile("cp.async.commit_group;" ::: "memory")
#define CPWAIT(n)   asm volatile("cp.async.wait_group %0;" :: "n"(n) : "memory")

// transposed cheb for k = 1,2 only (k=0 is the identity): [k-1][n][m pad 172]
__device__ __align__(16) float g_chebT[2 * NV * CPAD];

__global__ void prep_chebT(const float* __restrict__ cheb) {
    int idx = blockIdx.x * 256 + threadIdx.x;
    if (idx >= 2 * NV * CPAD) return;
    int j  = idx % CPAD;
    int kn = idx / CPAD;
    int n  = kn % NV;
    int k  = kn / NV + 1;
    g_chebT[idx] = (j < NV) ? cheb[((size_t)k * NV + n) * NV + j] : 0.0f;
}

// shared memory layout (float offsets)
#define WC_OFF   0
#define WCB_OFF  576
#define WRES_OFF 640
#define WRB_OFF  832
#define XRES_OFF 896                      // 512
#define CHS_OFF  1408                     // 170*172 = 29240
#define XS_OFF   1408                     // x slice 1530 (overlaps chs)
#define TM_OFF   (CHS_OFF + NV * CPAD)    // 30648; Tm[m][68] = 11560
#define V_OFF    (TM_OFF + NV * TMP)      // 42208; V[172][64] = 11008
#define THS_OFF  (V_OFF + CPAD * OO)      // 53216; thetaS 4096
#define SMEM_FLOATS (THS_OFF + HH * OO)   // 57312
#define SMEM_BYTES  (SMEM_FLOATS * 4)     // 229248 B

#define CHEB_CHUNKS  ((NV * CPAD) / 4)    // 7310
#define THETA_CHUNKS ((HH * OO) / 4)      // 1024

// ---- stage 2: V = Tm @ theta_k, 6x8 fp32 register tiles (c += 4) ----
__device__ __forceinline__ void stage2_run(const float* __restrict__ thk,
                                           const float* __restrict__ Tm,
                                           float* __restrict__ Vv,
                                           int o8s2, int m20, bool act2)
{
    if (!act2) return;
    int mr[R2];
    #pragma unroll
    for (int i = 0; i < R2; ++i) mr[i] = (m20 + i < NV) ? (m20 + i) : (NV - 1);
    ull a2[R2][4];
    #pragma unroll
    for (int i = 0; i < R2; ++i)
        #pragma unroll
        for (int p = 0; p < 4; ++p) a2[i][p] = 0ull;

    for (int c = 0; c < HH; c += 4) {
        ulonglong2 th0a = *(const ulonglong2*)(thk + (c + 0) * OO + o8s2);
        ulonglong2 th0b = *(const ulonglong2*)(thk + (c + 0) * OO + o8s2 + 4);
        ulonglong2 th1a = *(const ulonglong2*)(thk + (c + 1) * OO + o8s2);
        ulonglong2 th1b = *(const ulonglong2*)(thk + (c + 1) * OO + o8s2 + 4);
        ulonglong2 th2a = *(const ulonglong2*)(thk + (c + 2) * OO + o8s2);
        ulonglong2 th2b = *(const ulonglong2*)(thk + (c + 2) * OO + o8s2 + 4);
        ulonglong2 th3a = *(const ulonglong2*)(thk + (c + 3) * OO + o8s2);
        ulonglong2 th3b = *(const ulonglong2*)(thk + (c + 3) * OO + o8s2 + 4);
        #pragma unroll
        for (int i = 0; i < R2; ++i) {
            ulonglong2 tm4 = *(const ulonglong2*)(Tm + mr[i] * TMP + c);
            float2 t01 = f2un(tm4.x);
            float2 t23 = f2un(tm4.y);
            ull d0 = f2dup(t01.x), d1 = f2dup(t01.y);
            ull d2 = f2dup(t23.x), d3 = f2dup(t23.y);
            a2[i][0] = f2fma(d0, th0a.x, a2[i][0]);
            a2[i][1] = f2fma(d0, th0a.y, a2[i][1]);
            a2[i][2] = f2fma(d0, th0b.x, a2[i][2]);
            a2[i][3] = f2fma(d0, th0b.y, a2[i][3]);
            a2[i][0] = f2fma(d1, th1a.x, a2[i][0]);
            a2[i][1] = f2fma(d1, th1a.y, a2[i][1]);
            a2[i][2] = f2fma(d1, th1b.x, a2[i][2]);
            a2[i][3] = f2fma(d1, th1b.y, a2[i][3]);
            a2[i][0] = f2fma(d2, th2a.x, a2[i][0]);
            a2[i][1] = f2fma(d2, th2a.y, a2[i][1]);
            a2[i][2] = f2fma(d2, th2b.x, a2[i][2]);
            a2[i][3] = f2fma(d2, th2b.y, a2[i][3]);
            a2[i][0] = f2fma(d3, th3a.x, a2[i][0]);
            a2[i][1] = f2fma(d3, th3a.y, a2[i][1]);
            a2[i][2] = f2fma(d3, th3b.x, a2[i][2]);
            a2[i][3] = f2fma(d3, th3b.y, a2[i][3]);
        }
    }
    #pragma unroll
    for (int i = 0; i < R2; ++i) {
        int m = m20 + i;
        if (m < CPAD) {
            ulonglong2* dst = (ulonglong2*)(Vv + (size_t)m * OO + o8s2);
            dst[0] = make_ulonglong2(a2[i][0], a2[i][1]);
            dst[1] = make_ulonglong2(a2[i][2], a2[i][3]);
        }
    }
}

// ---- stage 3: acc += chs[n][m] * V[m][o16..+16) over [mlo,mhi) ----
// 10x16 tile; V rows loaded per-r (16 regs live) so acc(160)+cb(40)+v(16)
// stays within budget.
__device__ __forceinline__ void stage3_run(const float* __restrict__ chs,
                                           const float* __restrict__ Vv,
                                           ull (&acc)[S3R][8],
                                           const int* __restrict__ croff,
                                           int o16, int mlo, int mhi, bool act3)
{
    if (!act3) return;
    #pragma unroll 1
    for (int m = mlo; m < mhi; m += 4) {
        float4 cb[S3R];
        #pragma unroll
        for (int i = 0; i < S3R; ++i)
            cb[i] = *(const float4*)(chs + croff[i] + m);
        const float* vp = Vv + (size_t)m * OO + o16;
        #pragma unroll
        for (int r = 0; r < 4; ++r) {
            ulonglong2 va = *(const ulonglong2*)(vp + r * OO);
            ulonglong2 vb = *(const ulonglong2*)(vp + r * OO + 4);
            ulonglong2 vc = *(const ulonglong2*)(vp + r * OO + 8);
            ulonglong2 vd = *(const ulonglong2*)(vp + r * OO + 12);
            #pragma unroll
            for (int i = 0; i < S3R; ++i) {
                float cs = (r == 0) ? cb[i].x : (r == 1) ? cb[i].y
                         : (r == 2) ? cb[i].z : cb[i].w;
                ull d = f2dup(cs);
                acc[i][0] = f2fma(d, va.x, acc[i][0]);
                acc[i][1] = f2fma(d, va.y, acc[i][1]);
                acc[i][2] = f2fma(d, vb.x, acc[i][2]);
                acc[i][3] = f2fma(d, vb.y, acc[i][3]);
                acc[i][4] = f2fma(d, vc.x, acc[i][4]);
                acc[i][5] = f2fma(d, vc.y, acc[i][5]);
                acc[i][6] = f2fma(d, vd.x, acc[i][6]);
                acc[i][7] = f2fma(d, vd.y, acc[i][7]);
            }
        }
    }
}

__global__ void __launch_bounds__(NT, 1)
stgcn_fused_kernel(const float* __restrict__ x,
                   const float* __restrict__ theta,
                   const float* __restrict__ conv_w,
                   const float* __restrict__ conv_b,
                   const float* __restrict__ res_w,
                   const float* __restrict__ res_b,
                   float* __restrict__ out)
{
    extern __shared__ float sm[];
    float* wc   = sm + WC_OFF;
    float* wcb  = sm + WCB_OFF;
    float* wres = sm + WRES_OFF;
    float* wrb  = sm + WRB_OFF;
    float* xres = sm + XRES_OFF;
    float* xs   = sm + XS_OFF;
    float* chs  = sm + CHS_OFF;
    float* Tm   = sm + TM_OFF;
    float* Vv   = sm + V_OFF;
    float* ths  = sm + THS_OFF;
    const unsigned ths_u = s2u(ths);
    const unsigned chs_u = s2u(chs);

    const int t   = blockIdx.x;
    const int b   = blockIdx.y;
    const int tid = threadIdx.x;

    // G0: theta[0]
    for (int i = tid; i < THETA_CHUNKS; i += NT)
        CPA16(ths_u + i * 16, theta + (size_t)i * 4);
    CPCOMMIT();

    // ---------------- stage 0: xs + small weights ----------------
    for (int i = tid; i < FINq * 3 * NV; i += NT) {
        int f = i / (3 * NV);
        int r = i - f * (3 * NV);
        int s = r / NV;
        int m = r - s * NV;
        int tt = t + s - 1;
        float v = 0.0f;
        if (tt >= 0 && tt < TTq)
            v = x[((size_t)(b * FINq + f) * NV + m) * TTq + tt];
        xs[i] = v;
    }
    for (int i = tid; i < HH * FINq * 3; i += NT) wc[i] = conv_w[i];
    if (tid < OO * FINq)              wres[tid]      = res_w[tid];
    else if (tid >= 192 && tid < 256) wcb[tid - 192] = conv_b[tid - 192];
    if (tid < OO)                     wrb[tid]       = res_b[tid];
    __syncthreads();

    // ---------------- stage 1: temporal conv + ReLU -> Tm[m][c] ----------------
    for (int idx = tid; idx < NV * HH; idx += NT) {
        int m = idx >> 6;
        int c = idx & 63;
        float v = wcb[c];
        #pragma unroll
        for (int f = 0; f < FINq; ++f)
            #pragma unroll
            for (int s = 0; s < 3; ++s)
                v = fmaf(xs[(f * 3 + s) * NV + m], wc[(c * FINq + f) * 3 + s], v);
        Tm[m * TMP + c] = fmaxf(v, 0.0f);
    }
    for (int i = tid; i < FINq * NV; i += NT) {
        int f = i / NV;
        int n = i - f * NV;
        xres[i] = xs[(f * 3 + 1) * NV + n];
    }
    __syncthreads();     // xs reads + Tm writes done

    // G1: cheb[1] slice (overwrites xs region)
    for (int i = tid; i < CHEB_CHUNKS; i += NT)
        CPA16(chs_u + i * 16, g_chebT + (size_t)i * 4);
    CPCOMMIT();
    CPWAIT(1);           // theta[0] landed
    __syncthreads();

    // ---- thread mappings ----
    const int o8s2 = (tid & 7) * 8;
    const int rg2  = tid >> 3;
    const int m20  = rg2 * R2;
    const bool act2 = (m20 < NV);

    // stage 3: half by WARP PARITY so active warps cover all 4 SMSPs.
    const int wid  = tid >> 5;
    const int half = wid & 1;            // even warps: m[0,88), odd: m[88,172)
    const int htid = (wid >> 1) * 32 + (tid & 31);   // 0..127 per half
    const bool act3 = (htid < 68);       // 17 row-groups x 4 col-groups
    const int rg3  = htid >> 2;          // 0..16
    const int o16  = (htid & 3) * 16;
    const int n0   = rg3 * S3R;          // exact: 17*10 = 170
    const int mlo  = half ? 88 : 0;
    const int mhi  = half ? CPAD : 88;

    int croff[S3R];
    #pragma unroll
    for (int i = 0; i < S3R; ++i) croff[i] = (n0 + i) * CPAD;

    ull acc[S3R][8];
    #pragma unroll
    for (int i = 0; i < S3R; ++i)
        #pragma unroll
        for (int p = 0; p < 8; ++p) acc[i][p] = 0ull;

    // ================= k = 0 : cheb[0] = I, acc := V0 =================
    stage2_run(ths, Tm, Vv, o8s2, m20, act2);     // V0 = Tm @ theta0
    __syncthreads();                              // V0 visible; ths readers done

    {   // G2: theta[1]
        const float* tsrc = theta + (size_t)HH * OO;
        for (int i = tid; i < THETA_CHUNKS; i += NT)
            CPA16(ths_u + i * 16, tsrc + (size_t)i * 4);
        CPCOMMIT();
    }
    // acc init from V0 (even-warp half only; odd half sums its m-range)
    if (act3 && half == 0) {
        #pragma unroll
        for (int i = 0; i < S3R; ++i) {
            const ulonglong2* src = (const ulonglong2*)(Vv + (size_t)(n0 + i) * OO + o16);
            ulonglong2 p0 = src[0], p1 = src[1], p2 = src[2], p3 = src[3];
            acc[i][0] = p0.x; acc[i][1] = p0.y;
            acc[i][2] = p1.x; acc[i][3] = p1.y;
            acc[i][4] = p2.x; acc[i][5] = p2.y;
            acc[i][6] = p3.x; acc[i][7] = p3.y;
        }
    }
    CPWAIT(0);           // cheb[1] + theta[1] landed
    __syncthreads();     // V0 reads done + copies visible; Vv free

    // ================= k = 1 =================
    stage2_run(ths, Tm, Vv, o8s2, m20, act2);     // V1
    __syncthreads();                              // V1 visible; ths free
    {   // G3: theta[2]
        const float* tsrc = theta + (size_t)(2 * HH * OO);
        for (int i = tid; i < THETA_CHUNKS; i += NT)
            CPA16(ths_u + i * 16, tsrc + (size_t)i * 4);
        CPCOMMIT();
    }
    stage3_run(chs, Vv, acc, croff, o16, mlo, mhi, act3);   // += C1 @ V1
    __syncthreads();     // chs readers done
    {   // G4: cheb[2]
        const float* csrc = g_chebT + (size_t)NV * CPAD;
        for (int i = tid; i < CHEB_CHUNKS; i += NT)
            CPA16(chs_u + i * 16, csrc + (size_t)i * 4);
        CPCOMMIT();
    }
    CPWAIT(1);           // theta[2] ready (cheb[2] may pend)
    __syncthreads();

    // ================= k = 2 =================
    stage2_run(ths, Tm, Vv, o8s2, m20, act2);     // V2
    CPWAIT(0);           // cheb[2] landed
    __syncthreads();     // V2 + cheb[2] visible
    stage3_run(chs, Vv, acc, croff, o16, mlo, mhi, act3);   // += C2 @ V2

    // ---------------- cross-half reduce via chs region (now free) ----------------
    __syncthreads();
    if (act3 && half == 1) {
        #pragma unroll
        for (int i = 0; i < S3R; ++i) {
            ulonglong2* dst = (ulonglong2*)(chs + (size_t)(n0 + i) * OO + o16);
            dst[0] = make_ulonglong2(acc[i][0], acc[i][1]);
            dst[1] = make_ulonglong2(acc[i][2], acc[i][3]);
            dst[2] = make_ulonglong2(acc[i][4], acc[i][5]);
            dst[3] = make_ulonglong2(acc[i][6], acc[i][7]);
        }
    }
    __syncthreads();

    // ---------------- epilogue (half 0): add partner, relu + residual ----------------
    if (act3 && half == 0) {
        #pragma unroll
        for (int i = 0; i < S3R; ++i) {
            int n = n0 + i;
            const ulonglong2* src = (const ulonglong2*)(chs + (size_t)n * OO + o16);
            ulonglong2 p0 = src[0], p1 = src[1], p2 = src[2], p3 = src[3];
            acc[i][0] = f2add(acc[i][0], p0.x);
            acc[i][1] = f2add(acc[i][1], p0.y);
            acc[i][2] = f2add(acc[i][2], p1.x);
            acc[i][3] = f2add(acc[i][3], p1.y);
            acc[i][4] = f2add(acc[i][4], p2.x);
            acc[i][5] = f2add(acc[i][5], p2.y);
            acc[i][6] = f2add(acc[i][6], p3.x);
            acc[i][7] = f2add(acc[i][7], p3.y);
            float x0 = xres[n];
            float x1 = xres[NV + n];
            float x2 = xres[2 * NV + n];
            #pragma unroll
            for (int p = 0; p < 8; ++p) {
                float2 gv = f2un(acc[i][p]);
                int o0 = o16 + 2 * p;
                float r0 = wrb[o0] + x0 * wres[o0 * 3 + 0]
                                   + x1 * wres[o0 * 3 + 1]
                                   + x2 * wres[o0 * 3 + 2];
                float r1 = wrb[o0 + 1] + x0 * wres[(o0 + 1) * 3 + 0]
                                       + x1 * wres[(o0 + 1) * 3 + 1]
                                       + x2 * wres[(o0 + 1) * 3 + 2];
                out[((size_t)(b * OO + o0)     * NV + n) * TTq + t] = fmaxf(gv.x, 0.0f) + r0;
                out[((size_t)(b * OO + o0 + 1) * NV + n) * TTq + t] = fmaxf(gv.y, 0.0f) + r1;
            }
        }
    }
}

extern "C" void kernel_launch(void* const* d_in, const int* in_sizes, int n_in,
                              void* d_out, int out_size)
{
    (void)in_sizes; (void)n_in; (void)out_size;
    const float* x      = (const float*)d_in[0];
    // d_in[1] = adj (unused by forward)
    const float* cheb   = (const float*)d_in[2];
    const float* conv_w = (const float*)d_in[3];
    const float* conv_b = (const float*)d_in[4];
    const float* theta  = (const float*)d_in[5];
    const float* res_w  = (const float*)d_in[6];
    const float* res_b  = (const float*)d_in[7];
    float* out = (float*)d_out;

    prep_chebT<<<(2 * NV * CPAD + 255) / 256, 256>>>(cheb);

    cudaFuncSetAttribute(stgcn_fused_kernel,
                         cudaFuncAttributeMaxDynamicSharedMemorySize, SMEM_BYTES);

    dim3 grid(TTq, 16);   // 4608 CTAs, one per (b, t)
    stgcn_fused_kernel<<<grid, NT, SMEM_BYTES>>>(
        x, theta, conv_w, conv_b, res_w, res_b, out);
}